// round 6
// baseline (speedup 1.0000x reference)
#include <cuda_runtime.h>
#include <cuda_bf16.h>
#include <cstdint>

#define BB 16
#define SS 64
#define NNODE 128
#define FF 16
#define HH 64
#define EE 1024
#define ET 1152
#define LL 2
#define G3 192
#define NROWS (BB * SS * NNODE)   // 131072 rows of H

typedef unsigned long long u64;

__device__ __forceinline__ void ffma2(u64& d, u64 a, u64 b) {
    asm("fma.rn.f32x2 %0, %1, %2, %0;" : "+l"(d) : "l"(a), "l"(b));
}
__device__ __forceinline__ float f2sum(u64 v) {
    return __uint_as_float((unsigned)v) + __uint_as_float((unsigned)(v >> 32));
}
__device__ __forceinline__ u64 f2init(float lo) {
    return (u64)__float_as_uint(lo);
}
__device__ __forceinline__ void cp16(uint32_t dst, const void* src) {
    asm volatile("cp.async.cg.shared.global [%0], [%1], 16;" :: "r"(dst), "l"(src));
}

// ---------------- device scratch ----------------
__device__ float g_H0[(size_t)NROWS * HH];
__device__ float g_H1[(size_t)NROWS * HH];
__device__ float g_XL[(size_t)NROWS * HH];
__device__ float g_XR[(size_t)NROWS * HH];
__device__ float g_gi[(size_t)SS * BB * NNODE * G3];  // [s][b*128+n][j]
__device__ float g_hlast[(size_t)BB * NNODE * HH];
__device__ int   g_csr_off[NNODE + 1];
__device__ int   g_csr_src[ET];   // (tgt<<16) | src

// ---------------- CSR prep (deterministic) ----------------
__global__ void prep_kernel(const int* __restrict__ ei) {
    __shared__ int eis[2 * EE];
    __shared__ int cnt[NNODE];
    __shared__ int off[NNODE + 1];
    int t = threadIdx.x;  // 128
    for (int i = t; i < 2 * EE; i += 128) eis[i] = ei[i];
    __syncthreads();
    int c = 0;
    for (int e = 0; e < ET; e++) {
        int tg = (e < EE) ? eis[EE + e] : (e - EE);
        if (tg == t) c++;
    }
    cnt[t] = c;
    __syncthreads();
    if (t == 0) {
        int sum = 0;
        for (int n = 0; n < NNODE; n++) { off[n] = sum; sum += cnt[n]; }
        off[NNODE] = sum;
    }
    __syncthreads();
    g_csr_off[t] = off[t];
    if (t == 0) g_csr_off[NNODE] = off[NNODE];
    int pos = off[t];
    for (int e = 0; e < ET; e++) {
        int sr = (e < EE) ? eis[e] : (e - EE);
        int tg = (e < EE) ? eis[EE + e] : (e - EE);
        if (tg == t) { g_csr_src[pos] = sr | (t << 16); pos++; }
    }
}

// ---------------- proj: H0 = X @ inW^T + inb  (K=16) ----------------
__global__ void __launch_bounds__(512, 2) proj_kernel(
    const float* __restrict__ X, const float* __restrict__ inW,
    const float* __restrict__ inb, float* __restrict__ H)
{
    __shared__ __align__(16) float As[128 * 16];
    __shared__ __align__(16) float Ws[64 * 20];
    __shared__ float bs[64];
    const int t = threadIdx.x;
    const size_t rowbase = (size_t)blockIdx.x * 128;

    const float4* xs = (const float4*)(X + rowbase * FF);
    ((float4*)As)[t] = xs[t];                       // 512 float4 = 2048 floats
    for (int i = t; i < HH * FF; i += 512) {
        int hh = i >> 4, f = i & 15;
        Ws[hh * 20 + f] = inW[i];
    }
    if (t < HH) bs[t] = inb[t];
    __syncthreads();

    const int hh = t & 63;
    const int ng = t >> 6;
    float bia = bs[hh];
#pragma unroll
    for (int p = 0; p < 2; p++) {
        u64 acc[8];
#pragma unroll
        for (int i = 0; i < 8; i++) acc[i] = f2init(bia);
#pragma unroll
        for (int q4 = 0; q4 < 4; q4++) {
            ulonglong2 w2 = *(const ulonglong2*)&Ws[hh * 20 + 4 * q4];
#pragma unroll
            for (int i = 0; i < 8; i++) {
                int n = ng + 8 * (8 * p + i);
                ulonglong2 hp = *(const ulonglong2*)&As[n * 16 + 4 * q4];
                ffma2(acc[i], hp.x, w2.x);
                ffma2(acc[i], hp.y, w2.y);
            }
        }
#pragma unroll
        for (int i = 0; i < 8; i++) {
            int n = ng + 8 * (8 * p + i);
            H[(rowbase + n) * HH + hh] = f2sum(acc[i]);
        }
    }
}

// ---------------- dual GEMM: XL/XR = H @ W1/W2^T + b1/b2 (K=64) ----------------
// smem: As 8192 | W1s 4352 | W2s 4352 | biases 128  -> 67.4KB -> 2 CTAs/SM
#define DG_SMEM_BYTES ((8192 + 4352 * 2 + 128) * 4)

__global__ void __launch_bounds__(512, 2) gemm_dual_kernel(
    const float* __restrict__ Hin,
    const float* __restrict__ W1, const float* __restrict__ b1,
    const float* __restrict__ W2, const float* __restrict__ b2,
    float* __restrict__ C1, float* __restrict__ C2)
{
    extern __shared__ __align__(16) float dsm[];
    float* As  = dsm;
    float* W1s = dsm + 8192;
    float* W2s = W1s + 4352;
    float* b1s = W2s + 4352;
    float* b2s = b1s + 64;

    const int t = threadIdx.x;
    const size_t rowbase = (size_t)blockIdx.x * 128;

    const float4* hs = (const float4*)(Hin + rowbase * HH);
#pragma unroll
    for (int q = 0; q < 4; q++) ((float4*)As)[t + 512 * q] = hs[t + 512 * q];
    for (int i = t; i < HH * HH; i += 512) {
        int j = i >> 6, k = i & 63;
        W1s[j * 68 + k] = W1[i];
        W2s[j * 68 + k] = W2[i];
    }
    if (t < HH) { b1s[t] = b1[t]; b2s[t] = b2[t]; }
    __syncthreads();

    const int hh = t & 63;
    const int ng = t >> 6;
    const float blv = b1s[hh];
    const float brv = b2s[hh];
#pragma unroll
    for (int p = 0; p < 2; p++) {
        u64 accl[8], accr[8];
#pragma unroll
        for (int i = 0; i < 8; i++) { accl[i] = f2init(blv); accr[i] = f2init(brv); }
        for (int q4 = 0; q4 < 16; q4++) {
            ulonglong2 wl2 = *(const ulonglong2*)&W1s[hh * 68 + 4 * q4];
            ulonglong2 wr2 = *(const ulonglong2*)&W2s[hh * 68 + 4 * q4];
#pragma unroll
            for (int i = 0; i < 8; i++) {
                int n = ng + 8 * (8 * p + i);
                ulonglong2 hp = *(const ulonglong2*)&As[n * HH + 4 * q4];
                ffma2(accl[i], hp.x, wl2.x);
                ffma2(accl[i], hp.y, wl2.y);
                ffma2(accr[i], hp.x, wr2.x);
                ffma2(accr[i], hp.y, wr2.y);
            }
        }
#pragma unroll
        for (int i = 0; i < 8; i++) {
            int n = ng + 8 * (8 * p + i);
            C1[(rowbase + n) * HH + hh] = f2sum(accl[i]);
            C2[(rowbase + n) * HH + hh] = f2sum(accr[i]);
        }
    }
}

// ---------------- agg: scores + segment softmax + aggregate, per slice ----------------
// smem: xl 8192 | xr 8192 | ea 1152 | atts 64 | soff 132 | ssrc 1152  -> 75.5KB -> 2 CTAs/SM
#define AG_SMEM_BYTES ((8192 * 2 + 1152 + 64 + 132 + 1152) * 4)

__global__ void __launch_bounds__(512, 2) agg_kernel(
    const float* __restrict__ XLg, const float* __restrict__ XRg,
    const float* __restrict__ att, const float* __restrict__ bo,
    float* __restrict__ Hout)
{
    extern __shared__ __align__(16) float asm_[];
    float* xl   = asm_;
    float* xr   = asm_ + 8192;
    float* ea   = asm_ + 16384;
    float* atts = ea + 1152;
    int* soff   = (int*)(atts + 64);
    int* ssrc   = soff + 132;

    const int t = threadIdx.x;
    const size_t base = (size_t)blockIdx.x * NNODE * HH;

    const float4* xls = (const float4*)(XLg + base);
    const float4* xrs = (const float4*)(XRg + base);
#pragma unroll
    for (int q = 0; q < 4; q++) {
        ((float4*)xl)[t + 512 * q] = xls[t + 512 * q];
        ((float4*)xr)[t + 512 * q] = xrs[t + 512 * q];
    }
    for (int i = t; i <= NNODE; i += 512) soff[i] = g_csr_off[i];
    for (int i = t; i < ET; i += 512) ssrc[i] = g_csr_src[i];
    if (t < HH) atts[t] = att[t];
    __syncthreads();

    const int lane = t & 31;
    const int wid  = t >> 5;   // 0..15

    // edge attention scores
    for (int e = wid; e < ET; e += 16) {
        int pk = ssrc[e];
        int tg = pk >> 16;
        int sr = pk & 0xffff;
        float v1 = xl[sr * HH + lane]      + xr[tg * HH + lane];
        float v2 = xl[sr * HH + 32 + lane] + xr[tg * HH + 32 + lane];
        v1 = fmaxf(v1, 0.f) + 0.2f * fminf(v1, 0.f);
        v2 = fmaxf(v2, 0.f) + 0.2f * fminf(v2, 0.f);
        float sum = v1 * atts[lane] + v2 * atts[lane + 32];
#pragma unroll
        for (int o = 16; o; o >>= 1) sum += __shfl_xor_sync(0xffffffffu, sum, o);
        if (lane == 0) ea[e] = sum;
    }
    __syncthreads();

    // segment softmax + aggregation + bias + relu
    {
        float bo0 = bo[lane];
        float bo1 = bo[32 + lane];
        for (int n = wid; n < NNODE; n += 16) {
            int beg = soff[n], end = soff[n + 1];
            float m = -1e30f;
            for (int i = beg + lane; i < end; i += 32) m = fmaxf(m, ea[i]);
#pragma unroll
            for (int o = 16; o; o >>= 1) m = fmaxf(m, __shfl_xor_sync(0xffffffffu, m, o));
            float z = 0.f;
            for (int i = beg + lane; i < end; i += 32) {
                float p = __expf(ea[i] - m);
                ea[i] = p;
                z += p;
            }
#pragma unroll
            for (int o = 16; o; o >>= 1) z += __shfl_xor_sync(0xffffffffu, z, o);
            float inv = 1.f / z;
            float a0 = 0.f, a1 = 0.f;
            for (int i = beg; i < end; i++) {
                float al = ea[i] * inv;
                int sr = ssrc[i] & 0xffff;
                a0 = fmaf(al, xl[sr * HH + lane], a0);
                a1 = fmaf(al, xl[sr * HH + 32 + lane], a1);
            }
            a0 = fmaxf(a0 + bo0, 0.f);
            a1 = fmaxf(a1 + bo1, 0.f);
            Hout[base + n * HH + lane]      = a0;
            Hout[base + n * HH + 32 + lane] = a1;
        }
    }
}

// ---------------- gi: g_gi = H @ Wih^T + bih, permuted to [s][b*128+n][j] ----------------
// smem: As 8192 | WT 192*68=13056 | bs 192 -> 85.9KB -> 2 CTAs/SM
#define GI_SMEM_BYTES ((8192 + 13056 + 192) * 4)

__global__ void __launch_bounds__(512, 2) gi_kernel(
    const float* __restrict__ Hin,
    const float* __restrict__ Wih, const float* __restrict__ bih)
{
    extern __shared__ __align__(16) float gsm[];
    float* As = gsm;
    float* WT = gsm + 8192;
    float* bs = WT + 13056;

    const int t = threadIdx.x;
    const size_t rowbase = (size_t)blockIdx.x * 128;

    const float4* hs = (const float4*)(Hin + rowbase * HH);
#pragma unroll
    for (int q = 0; q < 4; q++) ((float4*)As)[t + 512 * q] = hs[t + 512 * q];
    for (int i = t; i < G3 * HH; i += 512) {
        int j = i >> 6, k = i & 63;
        WT[j * 68 + k] = Wih[i];
    }
    if (t < G3) bs[t] = bih[t];
    __syncthreads();

    const int hh = t & 63;
    const int ng = t >> 6;

#pragma unroll
    for (int jb = 0; jb < 3; jb++) {
        const int j = jb * 64 + hh;
        const float bj = bs[j];
#pragma unroll
        for (int p = 0; p < 2; p++) {
            u64 acc[8];
#pragma unroll
            for (int i = 0; i < 8; i++) acc[i] = f2init(bj);
            for (int q4 = 0; q4 < 16; q4++) {
                ulonglong2 w2 = *(const ulonglong2*)&WT[j * 68 + 4 * q4];
#pragma unroll
                for (int i = 0; i < 8; i++) {
                    int n = ng + 8 * (8 * p + i);
                    ulonglong2 hp = *(const ulonglong2*)&As[n * HH + 4 * q4];
                    ffma2(acc[i], hp.x, w2.x);
                    ffma2(acc[i], hp.y, w2.y);
                }
            }
#pragma unroll
            for (int i = 0; i < 8; i++) {
                size_t row = rowbase + ng + 8 * (8 * p + i);
                int s = (int)((row >> 7) & 63);
                int b = (int)(row >> 13);
                size_t rp = ((size_t)(s * BB + b) << 7) | (row & 127);
                g_gi[rp * G3 + j] = f2sum(acc[i]);
            }
        }
    }
}

// ---------------- GRU: GRB=8 rows/CTA, 256 thr, 2 CTAs/SM ----------------
#define GRB 8
// floats: hs 8*68=544 | gh 8*192=1536 | gis 2*8*192=3072
#define GR_HS  0
#define GR_GH  544
#define GR_GIS (544 + 1536)
#define GRU_SMEM_BYTES ((GR_GIS + 3072) * 4)

__global__ void __launch_bounds__(256, 2) gru_kernel(
    const float* __restrict__ Whh, const float* __restrict__ bhh)
{
    extern __shared__ __align__(16) float gsm[];
    float* hs  = gsm + GR_HS;
    float* gh  = gsm + GR_GH;
    float* gis = gsm + GR_GIS;

    const int t = threadIdx.x;
    const bool is_mv = (t < G3);
    const int j = is_mv ? t : 0;
    const int row0 = blockIdx.x * GRB;

    // Whh row j in registers as packed f32x2 pairs
    u64 w2[32];
    {
        const ulonglong2* wp = (const ulonglong2*)(Whh + j * HH);
#pragma unroll
        for (int q = 0; q < 16; q++) {
            ulonglong2 v = wp[q];
            w2[2 * q]     = v.x;
            w2[2 * q + 1] = v.y;
        }
    }
    const float bh = bhh[j];
    for (int i = t; i < GRB * 68; i += 256) hs[i] = 0.f;

    const uint32_t gis_su = (uint32_t)__cvta_generic_to_shared(gis);
    const int tp = t - G3;   // 0..63 for prefetchers
    // prologue: stage s=0 into gis[0] (all threads help)
    for (int c = t; c < GRB * 48; c += 256) {
        int r = c / 48, o4 = c % 48;
        cp16(gis_su + (r * G3 + o4 * 4) * 4, g_gi + ((size_t)row0 + r) * G3 + o4 * 4);
    }
    asm volatile("cp.async.commit_group;" ::: "memory");
    asm volatile("cp.async.wait_group 0;" ::: "memory");
    __syncthreads();

    for (int s = 0; s < SS; s++) {
        const int buf = s & 1;
        if (!is_mv && s + 1 < SS) {
            const size_t sb = (size_t)(s + 1) * (BB * NNODE) + row0;
            const uint32_t db = gis_su + ((buf ^ 1) * GRB * G3) * 4;
#pragma unroll
            for (int q = 0; q < 6; q++) {
                int c = tp + 64 * q;           // 0..383
                int r = c / 48, o4 = c % 48;
                cp16(db + (r * G3 + o4 * 4) * 4, g_gi + (sb + r) * G3 + o4 * 4);
            }
            asm volatile("cp.async.commit_group;" ::: "memory");
        }

        if (is_mv) {
            u64 acc[GRB];
#pragma unroll
            for (int r = 0; r < GRB; r++) acc[r] = f2init(bh);
#pragma unroll
            for (int q4 = 0; q4 < 16; q4++) {
#pragma unroll
                for (int r = 0; r < GRB; r++) {
                    ulonglong2 hp = *(const ulonglong2*)&hs[r * 68 + 4 * q4];
                    ffma2(acc[r], hp.x, w2[2 * q4]);
                    ffma2(acc[r], hp.y, w2[2 * q4 + 1]);
                }
            }
#pragma unroll
            for (int r = 0; r < GRB; r++) gh[r * G3 + j] = f2sum(acc[r]);
        }

        if (s + 1 < SS) asm volatile("cp.async.wait_group 1;" ::: "memory");
        else           asm volatile("cp.async.wait_group 0;" ::: "memory");
        __syncthreads();

        // combine: GRB*64 = 512 updates, 2 per thread
        const float* gib = gis + buf * GRB * G3;
#pragma unroll
        for (int u2 = 0; u2 < 2; u2++) {
            int i = t + 256 * u2;
            int r = i >> 6, hc = i & 63;
            float ir  = gib[r * G3 + hc];
            float iz  = gib[r * G3 + 64 + hc];
            float in_ = gib[r * G3 + 128 + hc];
            float hr_ = gh[r * G3 + hc];
            float hz  = gh[r * G3 + 64 + hc];
            float hn  = gh[r * G3 + 128 + hc];
            float rg = 1.f / (1.f + __expf(-(ir + hr_)));
            float zg = 1.f / (1.f + __expf(-(iz + hz)));
            float nx = in_ + rg * hn;
            nx = fminf(fmaxf(nx, -15.f), 15.f);
            float e = __expf(2.f * nx);
            float nn = (e - 1.f) / (e + 1.f);
            float h = hs[r * 68 + hc];
            hs[r * 68 + hc] = nn + zg * (h - nn);
        }
        __syncthreads();
    }

#pragma unroll
    for (int u2 = 0; u2 < 2; u2++) {
        int i = t + 256 * u2;
        int r = i >> 6, hc = i & 63;
        g_hlast[(size_t)(row0 + r) * HH + hc] = hs[r * 68 + hc];
    }
}

// ---------------- output heads ----------------
__global__ void __launch_bounds__(256) heads_kernel(
    const float* __restrict__ oW1, const float* __restrict__ ob1,
    const float* __restrict__ oW2, const float* __restrict__ ob2,
    const float* __restrict__ dW1, const float* __restrict__ db1,
    const float* __restrict__ dW2, const float* __restrict__ db2,
    float* __restrict__ out)
{
    __shared__ float oW1T[64 * 32], dW1T[64 * 32];
    __shared__ float oW2s[32], dW2s[32], ob1s[32], db1s[32];
    __shared__ float ob2s, db2s;
    const int t = threadIdx.x, lane = t & 31, wid = t >> 5;
    for (int i = t; i < 32 * 64; i += 256) {
        int j = i >> 6, k = i & 63;
        oW1T[k * 32 + j] = oW1[i];
        dW1T[k * 32 + j] = dW1[i];
    }
    if (t < 32) { oW2s[t] = oW2[t]; dW2s[t] = dW2[t]; ob1s[t] = ob1[t]; db1s[t] = db1[t]; }
    if (t == 0) { ob2s = ob2[0]; db2s = db2[0]; }
    __syncthreads();

    const int nwarps = gridDim.x * 8;
    for (int row = blockIdx.x * 8 + wid; row < BB * NNODE; row += nwarps) {
        float h0 = g_hlast[(size_t)row * HH + lane];
        float h1 = g_hlast[(size_t)row * HH + 32 + lane];
        float aO = ob1s[lane];
        float aD = db1s[lane];
#pragma unroll 8
        for (int k = 0; k < HH; k++) {
            float src = (k < 32) ? h0 : h1;
            float hk = __shfl_sync(0xffffffffu, src, k & 31);
            aO = fmaf(hk, oW1T[k * 32 + lane], aO);
            aD = fmaf(hk, dW1T[k * 32 + lane], aD);
        }
        aO = fmaxf(aO, 0.f) * oW2s[lane];
        aD = fmaxf(aD, 0.f) * dW2s[lane];
#pragma unroll
        for (int o = 16; o; o >>= 1) {
            aO += __shfl_xor_sync(0xffffffffu, aO, o);
            aD += __shfl_xor_sync(0xffffffffu, aD, o);
        }
        if (lane == 0) {
            out[row] = aO + ob2s;
            out[BB * NNODE + row] = aD + db2s;
        }
    }
}

// ---------------- launch ----------------
extern "C" void kernel_launch(void* const* d_in, const int* in_sizes, int n_in,
                              void* d_out, int out_size) {
    const float* x    = (const float*)d_in[0];
    const int*   ei   = (const int*)  d_in[1];
    const float* inW  = (const float*)d_in[2];
    const float* inb  = (const float*)d_in[3];
    const float* gWl  = (const float*)d_in[4];
    const float* gbl  = (const float*)d_in[5];
    const float* gWr  = (const float*)d_in[6];
    const float* gbr  = (const float*)d_in[7];
    const float* gatt = (const float*)d_in[8];
    const float* gbo  = (const float*)d_in[9];
    const float* Wih  = (const float*)d_in[10];
    const float* Whh  = (const float*)d_in[11];
    const float* bih  = (const float*)d_in[12];
    const float* bhh  = (const float*)d_in[13];
    const float* oW1  = (const float*)d_in[14];
    const float* ob1  = (const float*)d_in[15];
    const float* oW2  = (const float*)d_in[16];
    const float* ob2  = (const float*)d_in[17];
    const float* dW1  = (const float*)d_in[18];
    const float* db1  = (const float*)d_in[19];
    const float* dW2  = (const float*)d_in[20];
    const float* db2  = (const float*)d_in[21];

    float *H0, *H1, *XL, *XR;
    cudaGetSymbolAddress((void**)&H0, g_H0);
    cudaGetSymbolAddress((void**)&H1, g_H1);
    cudaGetSymbolAddress((void**)&XL, g_XL);
    cudaGetSymbolAddress((void**)&XR, g_XR);

    cudaFuncSetAttribute(gemm_dual_kernel, cudaFuncAttributeMaxDynamicSharedMemorySize, DG_SMEM_BYTES);
    cudaFuncSetAttribute(agg_kernel, cudaFuncAttributeMaxDynamicSharedMemorySize, AG_SMEM_BYTES);
    cudaFuncSetAttribute(gi_kernel, cudaFuncAttributeMaxDynamicSharedMemorySize, GI_SMEM_BYTES);
    cudaFuncSetAttribute(gru_kernel, cudaFuncAttributeMaxDynamicSharedMemorySize, GRU_SMEM_BYTES);

    const int NG = NROWS / 128;   // 1024 row-tile CTAs

    prep_kernel<<<1, 128>>>(ei);
    proj_kernel<<<NG, 512>>>(x, inW, inb, H0);
    // layer 0
    gemm_dual_kernel<<<NG, 512, DG_SMEM_BYTES>>>(H0, gWl, gbl, gWr, gbr, XL, XR);
    agg_kernel<<<BB * SS, 512, AG_SMEM_BYTES>>>(XL, XR, gatt, gbo, H1);
    // layer 1
    gemm_dual_kernel<<<NG, 512, DG_SMEM_BYTES>>>(H1, gWl + HH * HH, gbl + HH,
                                                 gWr + HH * HH, gbr + HH, XL, XR);
    agg_kernel<<<BB * SS, 512, AG_SMEM_BYTES>>>(XL, XR, gatt + HH, gbo + HH, H0);
    // gi + GRU + heads
    gi_kernel<<<NG, 512, GI_SMEM_BYTES>>>(H0, Wih, bih);
    gru_kernel<<<(BB * NNODE) / GRB, 256, GRU_SMEM_BYTES>>>(Whh, bhh);
    heads_kernel<<<256, 256>>>(oW1, ob1, oW2, ob2, dW1, db1, dW2, db2, (float*)d_out);
}